// round 2
// baseline (speedup 1.0000x reference)
#include <cuda_runtime.h>

#define N_TOK 81920
#define C 256
#define SIGMA 0.0001f
#define LEAK 0.2f

// scratch state (device globals: no allocation allowed in kernel_launch)
__device__ float g_h[N_TOK * C];    // current hidden state
__device__ float g_acc[N_TOK * C];  // per-layer axial-sum accumulator

// ---- packed f32x2 helpers (sm_103a) ----
__device__ __forceinline__ unsigned long long dup2(float w) {
    unsigned long long r;
    asm("mov.b64 %0, {%1, %1};" : "=l"(r) : "f"(w));
    return r;
}
__device__ __forceinline__ void fma2(unsigned long long& d, unsigned long long a, unsigned long long b) {
    asm("fma.rn.f32x2 %0, %1, %2, %0;" : "+l"(d) : "l"(a), "l"(b));
}
__device__ __forceinline__ float2 unpk(unsigned long long v) {
    float2 f;
    asm("mov.b64 {%0, %1}, %2;" : "=f"(f.x), "=f"(f.y) : "l"(v));
    return f;
}

// ---- encoder: h = tanh([x+sigma*noise, rand] @ W_enc) + pos_emb ----
__global__ void encode_kernel(const float* __restrict__ x, const float* __restrict__ noise,
                              const float* __restrict__ rnd, const float* __restrict__ Wenc,
                              const float* __restrict__ pos) {
    int t = blockIdx.x, c = threadIdx.x;
    float a = x[t] + SIGMA * noise[t];
    float r = rnd[t];
    float v = tanhf(a * Wenc[c] + r * Wenc[C + c]);
    g_h[t * C + c] = v + pos[(t % 160) * C + c];
}

// ---- fused axial attention ----
// T = sequence length along the attended axis, G = groups per block, AXIS in {1,2,3}
// mode: 0 -> g_acc = contrib ; 1 -> g_acc += contrib ; 2 -> g_h = leaky(g_acc + contrib)
template <int T, int G, int AXIS>
__global__ __launch_bounds__(256, 2) void axial_kernel(
    const float* __restrict__ Wq, const float* __restrict__ Wkv,
    const float* __restrict__ Wo, const float* __restrict__ bo, int mode) {
    constexpr int TT = T * G;
    static_assert(TT % 4 == 0, "token pairs must vectorize");

    extern __shared__ char smem_raw[];
    float* hsT   = (float*)smem_raw;        // [C][TT]  (transposed for f32x2 pair loads)
    float* qs    = hsT + C * TT;            // [TT][C]
    float* ks    = qs + TT * C;             // [TT][C]
    float* vs    = ks + TT * C;             // [TT][C]
    float* osT   = vs + TT * C;             // [C][TT]
    float* probs = osT + C * TT;            // [G][16][T][T]
    int*   s_tok = (int*)(probs + G * 16 * T * T);

    int tid = threadIdx.x;

    if (tid < TT) {
        int gi = tid / T, t = tid % T;
        int g = blockIdx.x * G + gi;
        int base, stride;
        if (AXIS == 1)      { base = (g / 20) * 160 + (g % 20); stride = 20; }
        else if (AXIS == 2) { int b = g / 40, r = g % 40;
                              base = b * 160 + (r / 5) * 20 + (r % 5); stride = 5; }
        else                { base = (g / 32) * 160 + (g % 32) * 5; stride = 1; }
        s_tok[tid] = base + t * stride;
    }
    __syncthreads();

    // load h tile transposed: hsT[c][tt]
    #pragma unroll
    for (int tt = 0; tt < TT; tt++)
        hsT[tid * TT + tt] = g_h[s_tok[tt] * C + tid];
    __syncthreads();

    // ---- QKV projection: thread tid owns output column tid of q, k, v ----
    {
        unsigned long long aq[TT / 2], ak[TT / 2], av[TT / 2];
        #pragma unroll
        for (int p = 0; p < TT / 2; p++) { aq[p] = 0ull; ak[p] = 0ull; av[p] = 0ull; }
        const float* wqp = Wq + tid;
        const float* wkp = Wkv + tid;
        const float* wvp = Wkv + C + tid;
        #pragma unroll 4
        for (int c = 0; c < C; c++) {
            unsigned long long wq2 = dup2(__ldg(wqp + c * C));
            unsigned long long wk2 = dup2(__ldg(wkp + c * 2 * C));
            unsigned long long wv2 = dup2(__ldg(wvp + c * 2 * C));
            const ulonglong2* hp = (const ulonglong2*)(hsT + c * TT);
            #pragma unroll
            for (int p2 = 0; p2 < TT / 4; p2++) {
                ulonglong2 hv = hp[p2];
                fma2(aq[2 * p2], hv.x, wq2); fma2(aq[2 * p2 + 1], hv.y, wq2);
                fma2(ak[2 * p2], hv.x, wk2); fma2(ak[2 * p2 + 1], hv.y, wk2);
                fma2(av[2 * p2], hv.x, wv2); fma2(av[2 * p2 + 1], hv.y, wv2);
            }
        }
        #pragma unroll
        for (int p = 0; p < TT / 2; p++) {
            float2 fq = unpk(aq[p]), fk = unpk(ak[p]), fv = unpk(av[p]);
            int r0 = (2 * p) * C + tid, r1 = r0 + C;
            qs[r0] = fq.x; qs[r1] = fq.y;
            ks[r0] = fk.x; ks[r1] = fk.y;
            vs[r0] = fv.x; vs[r1] = fv.y;
        }
    }
    __syncthreads();

    // ---- attention logits: dots[g][head][tq][ts] = (q . k) / sqrt(16) ----
    for (int i = tid; i < G * 16 * T * T; i += 256) {
        int gi = i / (16 * T * T);
        int r  = i % (16 * T * T);
        int head = r / (T * T);
        int rr = r % (T * T);
        int tq = rr / T, ts = rr % T;
        const float* qrow = qs + (gi * T + tq) * C + head * 16;
        const float* krow = ks + (gi * T + ts) * C + head * 16;
        float s = 0.f;
        #pragma unroll
        for (int d = 0; d < 16; d++) s += qrow[d] * krow[d];
        probs[i] = 0.25f * s;
    }
    __syncthreads();

    // ---- softmax over last dim ----
    for (int i = tid; i < G * 16 * T; i += 256) {
        float* row = probs + i * T;
        float m = row[0];
        #pragma unroll
        for (int s = 1; s < T; s++) m = fmaxf(m, row[s]);
        float e[T];
        float sum = 0.f;
        #pragma unroll
        for (int s = 0; s < T; s++) { e[s] = expf(row[s] - m); sum += e[s]; }
        float inv = 1.f / sum;
        #pragma unroll
        for (int s = 0; s < T; s++) row[s] = e[s] * inv;
    }
    __syncthreads();

    // ---- o = probs @ v, stored transposed for the out-projection ----
    {
        int head = tid >> 4;
        #pragma unroll
        for (int tt = 0; tt < TT; tt++) {
            int gi = tt / T, t = tt % T;
            const float* pr = probs + ((gi * 16 + head) * T + t) * T;
            float o = 0.f;
            #pragma unroll
            for (int s = 0; s < T; s++) o += pr[s] * vs[(gi * T + s) * C + tid];
            osT[tid * TT + tt] = o;
        }
    }
    __syncthreads();

    // ---- out-projection + bias + accumulate ----
    {
        unsigned long long acc[TT / 2];
        #pragma unroll
        for (int p = 0; p < TT / 2; p++) acc[p] = 0ull;
        const float* wop = Wo + tid;
        #pragma unroll 4
        for (int c = 0; c < C; c++) {
            unsigned long long w2 = dup2(__ldg(wop + c * C));
            const ulonglong2* op = (const ulonglong2*)(osT + c * TT);
            #pragma unroll
            for (int p2 = 0; p2 < TT / 4; p2++) {
                ulonglong2 ov = op[p2];
                fma2(acc[2 * p2], ov.x, w2);
                fma2(acc[2 * p2 + 1], ov.y, w2);
            }
        }
        float bias = __ldg(bo + tid);
        #pragma unroll
        for (int p = 0; p < TT / 2; p++) {
            float2 f = unpk(acc[p]);
            float v0 = f.x + bias, v1 = f.y + bias;
            int i0 = s_tok[2 * p] * C + tid;
            int i1 = s_tok[2 * p + 1] * C + tid;
            if (mode == 0)      { g_acc[i0] = v0;  g_acc[i1] = v1; }
            else if (mode == 1) { g_acc[i0] += v0; g_acc[i1] += v1; }
            else {
                float s0 = g_acc[i0] + v0, s1 = g_acc[i1] + v1;
                g_h[i0] = s0 >= 0.f ? s0 : LEAK * s0;
                g_h[i1] = s1 >= 0.f ? s1 : LEAK * s1;
            }
        }
    }
}

// ---- decoder: out = sigmoid(h @ Wd + bd) ----
__global__ void decode_kernel(const float* __restrict__ Wd, const float* __restrict__ bd,
                              float* __restrict__ out) {
    int t = blockIdx.x * 8 + (threadIdx.x >> 5);
    int lane = threadIdx.x & 31;
    const float* hr = g_h + t * C;
    float s = 0.f;
    #pragma unroll
    for (int c = lane; c < C; c += 32) s += hr[c] * Wd[c];
    #pragma unroll
    for (int o = 16; o > 0; o >>= 1) s += __shfl_xor_sync(0xffffffffu, s, o);
    if (lane == 0) out[t] = 1.f / (1.f + expf(-(s + bd[0])));
}

static constexpr int smem_bytes(int T, int G) {
    int TT = T * G;
    return TT * C * 5 * 4 + G * 16 * T * T * 4 + TT * 4;
}

extern "C" void kernel_launch(void* const* d_in, const int* in_sizes, int n_in,
                              void* d_out, int out_size) {
    const float* x     = (const float*)d_in[0];
    const float* noise = (const float*)d_in[1];
    const float* rnd   = (const float*)d_in[2];
    const float* Wenc  = (const float*)d_in[3];
    const float* pos   = (const float*)d_in[4];
    const float* Wq    = (const float*)d_in[5];
    const float* Wkv   = (const float*)d_in[6];
    const float* Wo    = (const float*)d_in[7];
    const float* bo    = (const float*)d_in[8];
    const float* Wd    = (const float*)d_in[9];
    const float* bd    = (const float*)d_in[10];
    float* out = (float*)d_out;

    constexpr int SM1 = smem_bytes(8, 2);  // axis 1: T=8,  G=2, TT=16 -> 10240 groups / 5120 blocks
    constexpr int SM2 = smem_bytes(4, 4);  // axis 2: T=4,  G=4, TT=16 -> 20480 groups / 5120 blocks
    constexpr int SM3 = smem_bytes(5, 4);  // axis 3: T=5,  G=4, TT=20 -> 16384 groups / 4096 blocks

    // attribute set is idempotent; also applied on the pre-capture correctness call
    cudaFuncSetAttribute(axial_kernel<8, 2, 1>, cudaFuncAttributeMaxDynamicSharedMemorySize, SM1);
    cudaFuncSetAttribute(axial_kernel<4, 4, 2>, cudaFuncAttributeMaxDynamicSharedMemorySize, SM2);
    cudaFuncSetAttribute(axial_kernel<5, 4, 3>, cudaFuncAttributeMaxDynamicSharedMemorySize, SM3);

    encode_kernel<<<N_TOK, 256>>>(x, noise, rnd, Wenc, pos);

    for (int l = 0; l < 2; l++) {
        const float* wq0 = Wq  + (l * 3 + 0) * C * C;
        const float* wk0 = Wkv + (l * 3 + 0) * C * 2 * C;
        const float* wo0 = Wo  + (l * 3 + 0) * C * C;
        const float* bo0 = bo  + (l * 3 + 0) * C;
        axial_kernel<8, 2, 1><<<5120, 256, SM1>>>(wq0, wk0, wo0, bo0, 0);

        const float* wq1 = Wq  + (l * 3 + 1) * C * C;
        const float* wk1 = Wkv + (l * 3 + 1) * C * 2 * C;
        const float* wo1 = Wo  + (l * 3 + 1) * C * C;
        const float* bo1 = bo  + (l * 3 + 1) * C;
        axial_kernel<4, 4, 2><<<5120, 256, SM2>>>(wq1, wk1, wo1, bo1, 1);

        const float* wq2 = Wq  + (l * 3 + 2) * C * C;
        const float* wk2 = Wkv + (l * 3 + 2) * C * 2 * C;
        const float* wo2 = Wo  + (l * 3 + 2) * C * C;
        const float* bo2 = bo  + (l * 3 + 2) * C;
        axial_kernel<5, 4, 3><<<4096, 256, SM3>>>(wq2, wk2, wo2, bo2, 2);
    }

    decode_kernel<<<10240, 256>>>(Wd, bd, out);
}

// round 7
// speedup vs baseline: 1.2295x; 1.2295x over previous
#include <cuda_runtime.h>
#include <cuda_bf16.h>
#include <cstdint>

#define N_TOK 81920
#define C 256
#define SIGMA 0.0001f
#define LEAK 0.2f

// ---- scratch (device globals: no allocs allowed) ----
__device__ float g_h[N_TOK * C];       // hidden state (fp32)
__device__ float g_acc[N_TOK * C];     // axial-sum accumulator
__device__ float g_qkv[N_TOK * 768];   // q|k|v scratch (fp32)
__device__ float g_o[N_TOK * C];       // attention output scratch (fp32)

// ============================================================ helpers
__device__ __forceinline__ void split2(float a, float b, uint32_t& hp, uint32_t& lp) {
    __nv_bfloat16 ha = __float2bfloat16(a), hb = __float2bfloat16(b);
    float ra = a - __bfloat162float(ha), rb = b - __bfloat162float(hb);
    __nv_bfloat16 la = __float2bfloat16(ra), lb = __float2bfloat16(rb);
    hp = (uint32_t)__bfloat16_as_ushort(ha) | ((uint32_t)__bfloat16_as_ushort(hb) << 16);
    lp = (uint32_t)__bfloat16_as_ushort(la) | ((uint32_t)__bfloat16_as_ushort(lb) << 16);
}
__device__ __forceinline__ void split1(float a, uint16_t& h, uint16_t& l) {
    __nv_bfloat16 ha = __float2bfloat16(a);
    float ra = a - __bfloat162float(ha);
    __nv_bfloat16 la = __float2bfloat16(ra);
    h = __bfloat16_as_ushort(ha);
    l = __bfloat16_as_ushort(la);
}
__device__ __forceinline__ void mma_bf16(float* d, const uint32_t* a, const uint32_t* b) {
    asm volatile(
        "mma.sync.aligned.m16n8k16.row.col.f32.bf16.bf16.f32 "
        "{%0,%1,%2,%3}, {%4,%5,%6,%7}, {%8,%9}, {%0,%1,%2,%3};"
        : "+f"(d[0]), "+f"(d[1]), "+f"(d[2]), "+f"(d[3])
        : "r"(a[0]), "r"(a[1]), "r"(a[2]), "r"(a[3]), "r"(b[0]), "r"(b[1]));
}

// ---- smem layout for gemm3 (bf16 elements, rows padded to 72 = 144B stride) ----
#define LDS_PAD 72
#define SM_AH_OFF 0                          // A hi: 128 x 72 bf16 = 18432 B
#define SM_AL_OFF 18432                      // A lo
#define SM_BH_OFF 36864                      // B hi (transposed [n][k]): 64 x 72 = 9216 B
#define SM_BL_OFF 46080
#define SMEM_GEMM 55296

// ============================================================ encoder
__global__ void encode_kernel(const float* __restrict__ x, const float* __restrict__ noise,
                              const float* __restrict__ rnd, const float* __restrict__ Wenc,
                              const float* __restrict__ pos) {
    int t = blockIdx.x, c = threadIdx.x;
    float a = x[t] + SIGMA * noise[t];
    float r = rnd[t];
    float v = tanhf(a * Wenc[c] + r * Wenc[C + c]);
    g_h[t * C + c] = v + pos[(t % 160) * C + c];
}

// ============================================================ warp-MMA GEMM
// D[128 x 64] = A[128 x 256] @ W[256 x 64-chunk], 3-term bf16 hi/lo split.
// MODE 0: A=g_h,  dst=g_qkv (row stride 768), no bias
// MODE 1: A=g_o,  g_acc  = D + bias
// MODE 2: A=g_o,  g_acc += D + bias
// MODE 3: A=g_o,  g_h    = leaky(g_acc + D + bias)
template <int MODE>
__global__ __launch_bounds__(256, 2) void gemm3(
    const float* __restrict__ B0, int ldb0, int nsplit,
    const float* __restrict__ B1, int ldb1, const float* __restrict__ bias) {
    extern __shared__ char sm[];
    __nv_bfloat16* Ah = (__nv_bfloat16*)(sm + SM_AH_OFF);
    __nv_bfloat16* Al = (__nv_bfloat16*)(sm + SM_AL_OFF);
    __nv_bfloat16* Bh = (__nv_bfloat16*)(sm + SM_BH_OFF);
    __nv_bfloat16* Bl = (__nv_bfloat16*)(sm + SM_BL_OFF);

    int tid = threadIdx.x, wid = tid >> 5, lane = tid & 31;
    int g = lane >> 2, t4 = lane & 3;
    int wm = (wid >> 1) * 32;   // warp m offset within 128
    int wn = (wid & 1) * 32;    // warp n offset within 64
    int nc = blockIdx.x, m0 = blockIdx.y * 128;
    const float* A = (MODE == 0) ? g_h : g_o;
    const float* B;
    int ldb;
    if (nc < nsplit) { B = B0 + nc * 64; ldb = ldb0; }
    else             { B = B1 + (nc - nsplit) * 64; ldb = ldb1; }

    float d[2][4][4];
    #pragma unroll
    for (int mi = 0; mi < 2; mi++)
        #pragma unroll
        for (int ni = 0; ni < 4; ni++)
            #pragma unroll
            for (int r = 0; r < 4; r++) d[mi][ni][r] = 0.f;

    for (int kc = 0; kc < 4; kc++) {
        int k0 = kc * 64;
        if (kc) __syncthreads();
        // ---- stage A chunk [128 rows x 64 K] -> bf16 hi/lo ----
        #pragma unroll
        for (int i = 0; i < 8; i++) {
            int f4 = tid + i * 256;
            int row = f4 >> 4;
            int c4 = (f4 & 15) << 2;
            float4 v = *(const float4*)(A + (m0 + row) * 256 + k0 + c4);
            uint32_t h0, l0, h1, l1;
            split2(v.x, v.y, h0, l0);
            split2(v.z, v.w, h1, l1);
            *(uint2*)(Ah + row * LDS_PAD + c4) = make_uint2(h0, h1);
            *(uint2*)(Al + row * LDS_PAD + c4) = make_uint2(l0, l1);
        }
        // ---- stage B chunk [64 K x 64 N] transposed to [n][k] bf16 hi/lo ----
        #pragma unroll
        for (int i = 0; i < 8; i++) {
            int f2 = tid + i * 256;
            int kl = f2 >> 5;           // 0..63
            int np = (f2 & 31) << 1;    // 0..62
            float2 w = *(const float2*)(B + (k0 + kl) * ldb + np);
            uint16_t h0, l0, h1, l1;
            split1(w.x, h0, l0);
            split1(w.y, h1, l1);
            Bh[np * LDS_PAD + kl] = __ushort_as_bfloat16(h0);
            Bh[(np + 1) * LDS_PAD + kl] = __ushort_as_bfloat16(h1);
            Bl[np * LDS_PAD + kl] = __ushort_as_bfloat16(l0);
            Bl[(np + 1) * LDS_PAD + kl] = __ushort_as_bfloat16(l1);
        }
        __syncthreads();

        // ---- warp MMA over this 64-K chunk ----
        #pragma unroll
        for (int ks = 0; ks < 4; ks++) {
            int kb = ks * 16;
            uint32_t ah[2][4], al[2][4], bh[4][2], bl[4][2];
            #pragma unroll
            for (int mi = 0; mi < 2; mi++) {
                int r0 = wm + mi * 16 + g;
                ah[mi][0] = *(const uint32_t*)(Ah + r0 * LDS_PAD + kb + 2 * t4);
                ah[mi][1] = *(const uint32_t*)(Ah + (r0 + 8) * LDS_PAD + kb + 2 * t4);
                ah[mi][2] = *(const uint32_t*)(Ah + r0 * LDS_PAD + kb + 8 + 2 * t4);
                ah[mi][3] = *(const uint32_t*)(Ah + (r0 + 8) * LDS_PAD + kb + 8 + 2 * t4);
                al[mi][0] = *(const uint32_t*)(Al + r0 * LDS_PAD + kb + 2 * t4);
                al[mi][1] = *(const uint32_t*)(Al + (r0 + 8) * LDS_PAD + kb + 2 * t4);
                al[mi][2] = *(const uint32_t*)(Al + r0 * LDS_PAD + kb + 8 + 2 * t4);
                al[mi][3] = *(const uint32_t*)(Al + (r0 + 8) * LDS_PAD + kb + 8 + 2 * t4);
            }
            #pragma unroll
            for (int ni = 0; ni < 4; ni++) {
                int nr = wn + ni * 8 + g;
                bh[ni][0] = *(const uint32_t*)(Bh + nr * LDS_PAD + kb + 2 * t4);
                bh[ni][1] = *(const uint32_t*)(Bh + nr * LDS_PAD + kb + 8 + 2 * t4);
                bl[ni][0] = *(const uint32_t*)(Bl + nr * LDS_PAD + kb + 2 * t4);
                bl[ni][1] = *(const uint32_t*)(Bl + nr * LDS_PAD + kb + 8 + 2 * t4);
            }
            #pragma unroll
            for (int mi = 0; mi < 2; mi++)
                #pragma unroll
                for (int ni = 0; ni < 4; ni++) {
                    mma_bf16(d[mi][ni], ah[mi], bh[ni]);
                    mma_bf16(d[mi][ni], al[mi], bh[ni]);
                    mma_bf16(d[mi][ni], ah[mi], bl[ni]);
                }
        }
    }

    // ---- epilogue: registers -> global, fused bias/accum/leaky ----
    #pragma unroll
    for (int mi = 0; mi < 2; mi++) {
        #pragma unroll
        for (int ni = 0; ni < 4; ni++) {
            #pragma unroll
            for (int half = 0; half < 2; half++) {
                int row = m0 + wm + mi * 16 + g + half * 8;
                int col = wn + ni * 8 + 2 * t4;
                float v0 = d[mi][ni][half * 2];
                float v1 = d[mi][ni][half * 2 + 1];
                if (MODE == 0) {
                    *(float2*)(g_qkv + row * 768 + nc * 64 + col) = make_float2(v0, v1);
                } else {
                    int n0 = nc * 64 + col;
                    v0 += __ldg(bias + n0);
                    v1 += __ldg(bias + n0 + 1);
                    float* ap = g_acc + row * 256 + n0;
                    if (MODE == 1) {
                        *(float2*)ap = make_float2(v0, v1);
                    } else if (MODE == 2) {
                        float2 a = *(const float2*)ap;
                        *(float2*)ap = make_float2(a.x + v0, a.y + v1);
                    } else {
                        float2 a = *(const float2*)ap;
                        float s0 = a.x + v0, s1 = a.y + v1;
                        *(float2*)(g_h + row * 256 + n0) =
                            make_float2(s0 >= 0.f ? s0 : LEAK * s0, s1 >= 0.f ? s1 : LEAK * s1);
                    }
                }
            }
        }
    }
}

// ============================================================ attention (fp32)
// reads g_qkv, writes g_o. Per-group softmax-attention; grouping per AXIS.
template <int T, int G, int AXIS>
__global__ __launch_bounds__(256, 2) void attn_kernel() {
    constexpr int TT = T * G;
    extern __shared__ char smem_raw[];
    float* qs = (float*)smem_raw;       // [TT][256]
    float* ks = qs + TT * C;
    float* vs = ks + TT * C;
    float* probs = vs + TT * C;         // [G][16][T][T]
    int* s_tok = (int*)(probs + G * 16 * T * T);

    int tid = threadIdx.x;

    if (tid < TT) {
        int gi = tid / T, t = tid % T;
        int g = blockIdx.x * G + gi;
        int base, stride;
        if (AXIS == 1)      { base = (g / 20) * 160 + (g % 20); stride = 20; }
        else if (AXIS == 2) { int b = g / 40, r = g % 40;
                              base = b * 160 + (r / 5) * 20 + (r % 5); stride = 5; }
        else                { base = (g / 32) * 160 + (g % 32) * 5; stride = 1; }
        s_tok[tid] = base + t * stride;
    }
    __syncthreads();

    #pragma unroll
    for (int r = 0; r < TT; r++) {
        int base = s_tok[r] * 768;
        qs[r * C + tid] = g_qkv[base + tid];
        ks[r * C + tid] = g_qkv[base + 256 + tid];
        vs[r * C + tid] = g_qkv[base + 512 + tid];
    }
    __syncthreads();

    for (int i = tid; i < G * 16 * T * T; i += 256) {
        int gi = i / (16 * T * T);
        int r = i % (16 * T * T);
        int head = r / (T * T);
        int rr = r % (T * T);
        int tq = rr / T, ts = rr % T;
        const float* qrow = qs + (gi * T + tq) * C + head * 16;
        const float* krow = ks + (gi * T + ts) * C + head * 16;
        float s = 0.f;
        #pragma unroll
        for (int d = 0; d < 16; d++) s += qrow[d] * krow[d];
        probs[i] = 0.25f * s;
    }
    __syncthreads();

    for (int i = tid; i < G * 16 * T; i += 256) {
        float* row = probs + i * T;
        float m = row[0];
        #pragma unroll
        for (int s = 1; s < T; s++) m = fmaxf(m, row[s]);
        float e[T];
        float sum = 0.f;
        #pragma unroll
        for (int s = 0; s < T; s++) { e[s] = expf(row[s] - m); sum += e[s]; }
        float inv = 1.f / sum;
        #pragma unroll
        for (int s = 0; s < T; s++) row[s] = e[s] * inv;
    }
    __syncthreads();

    int head = tid >> 4;
    #pragma unroll
    for (int tt = 0; tt < TT; tt++) {
        int gi = tt / T, t = tt % T;
        const float* pr = probs + ((gi * 16 + head) * T + t) * T;
        float o = 0.f;
        #pragma unroll
        for (int s = 0; s < T; s++) o += pr[s] * vs[(gi * T + s) * C + tid];
        g_o[s_tok[tt] * C + tid] = o;
    }
}

// ============================================================ decoder
__global__ void decode_kernel(const float* __restrict__ Wd, const float* __restrict__ bd,
                              float* __restrict__ out) {
    int t = blockIdx.x * 8 + (threadIdx.x >> 5);
    int lane = threadIdx.x & 31;
    const float* hr = g_h + t * C;
    float s = 0.f;
    #pragma unroll
    for (int c = lane; c < C; c += 32) s += hr[c] * Wd[c];
    #pragma unroll
    for (int o = 16; o > 0; o >>= 1) s += __shfl_xor_sync(0xffffffffu, s, o);
    if (lane == 0) out[t] = 1.f / (1.f + expf(-(s + bd[0])));
}

// ============================================================ launch
static constexpr int attn_smem(int T, int G) {
    int TT = T * G;
    return TT * C * 3 * 4 + G * 16 * T * T * 4 + TT * 4;
}

extern "C" void kernel_launch(void* const* d_in, const int* in_sizes, int n_in,
                              void* d_out, int out_size) {
    const float* x     = (const float*)d_in[0];
    const float* noise = (const float*)d_in[1];
    const float* rnd   = (const float*)d_in[2];
    const float* Wenc  = (const float*)d_in[3];
    const float* pos   = (const float*)d_in[4];
    const float* Wq    = (const float*)d_in[5];
    const float* Wkv   = (const float*)d_in[6];
    const float* Wo    = (const float*)d_in[7];
    const float* bo    = (const float*)d_in[8];
    const float* Wd    = (const float*)d_in[9];
    const float* bd    = (const float*)d_in[10];
    float* out = (float*)d_out;

    constexpr int SA1 = attn_smem(8, 2);
    constexpr int SA2 = attn_smem(4, 4);
    constexpr int SA3 = attn_smem(5, 4);

    cudaFuncSetAttribute(gemm3<0>, cudaFuncAttributeMaxDynamicSharedMemorySize, SMEM_GEMM);
    cudaFuncSetAttribute(gemm3<1>, cudaFuncAttributeMaxDynamicSharedMemorySize, SMEM_GEMM);
    cudaFuncSetAttribute(gemm3<2>, cudaFuncAttributeMaxDynamicSharedMemorySize, SMEM_GEMM);
    cudaFuncSetAttribute(gemm3<3>, cudaFuncAttributeMaxDynamicSharedMemorySize, SMEM_GEMM);
    cudaFuncSetAttribute(attn_kernel<8, 2, 1>, cudaFuncAttributeMaxDynamicSharedMemorySize, SA1);
    cudaFuncSetAttribute(attn_kernel<4, 4, 2>, cudaFuncAttributeMaxDynamicSharedMemorySize, SA2);
    cudaFuncSetAttribute(attn_kernel<5, 4, 3>, cudaFuncAttributeMaxDynamicSharedMemorySize, SA3);

    encode_kernel<<<N_TOK, 256>>>(x, noise, rnd, Wenc, pos);

    for (int l = 0; l < 2; l++) {
        for (int a = 0; a < 3; a++) {
            int w = l * 3 + a;
            const float* wq  = Wq  + w * C * C;
            const float* wkv = Wkv + w * C * 2 * C;
            const float* wo  = Wo  + w * C * C;
            const float* bb  = bo  + w * C;

            // qkv = h @ [Wq | Wkv]  (12 n-chunks of 64)
            gemm3<0><<<dim3(12, 640), 256, SMEM_GEMM>>>(wq, C, 4, wkv, 2 * C, nullptr);

            if (a == 0)      attn_kernel<8, 2, 1><<<5120, 256, SA1>>>();
            else if (a == 1) attn_kernel<4, 4, 2><<<5120, 256, SA2>>>();
            else             attn_kernel<5, 4, 3><<<4096, 256, SA3>>>();

            // contrib = o @ Wo + bo, fused with accumulate / leaky
            if (a == 0)      gemm3<1><<<dim3(4, 640), 256, SMEM_GEMM>>>(wo, C, 4, wo, C, bb);
            else if (a == 1) gemm3<2><<<dim3(4, 640), 256, SMEM_GEMM>>>(wo, C, 4, wo, C, bb);
            else             gemm3<3><<<dim3(4, 640), 256, SMEM_GEMM>>>(wo, C, 4, wo, C, bb);
        }
    }

    decode_kernel<<<10240, 256>>>(Wd, bd, out);
}

// round 8
// speedup vs baseline: 2.1858x; 1.7778x over previous
#include <cuda_runtime.h>
#include <cuda_bf16.h>
#include <cstdint>

#define N_TOK 81920
#define C 256
#define SIGMA 0.0001f
#define LEAK 0.2f

// ---- scratch (device globals: no allocs allowed) ----
__device__ float g_h[N_TOK * C];          // final hidden (for decode)
__device__ float g_acc[N_TOK * C];        // axial-sum accumulator
__device__ float g_qkv[N_TOK * 768];      // q|k|v scratch (fp32)
__device__ __nv_bfloat16 g_hh[N_TOK * C]; // hidden state hi/lo split (bf16)
__device__ __nv_bfloat16 g_hl[N_TOK * C];
__device__ __nv_bfloat16 g_oh[N_TOK * C]; // attn output hi/lo split (bf16)
__device__ __nv_bfloat16 g_ol[N_TOK * C];
#define W_TOTAL 1572864                   // Wq(393216) | Wkv(786432) | Wo(393216)
#define WKV_BASE 393216
#define WO_BASE 1179648
__device__ __nv_bfloat16 g_wh[W_TOTAL];
__device__ __nv_bfloat16 g_wl[W_TOTAL];

// ============================================================ helpers
__device__ __forceinline__ void split1(float a, uint16_t& h, uint16_t& l) {
    __nv_bfloat16 ha = __float2bfloat16(a);
    float ra = a - __bfloat162float(ha);
    __nv_bfloat16 la = __float2bfloat16(ra);
    h = __bfloat16_as_ushort(ha);
    l = __bfloat16_as_ushort(la);
}
__device__ __forceinline__ uint32_t s2u(const void* p) {
    uint32_t a;
    asm("{ .reg .u64 t; cvta.to.shared.u64 t, %1; cvt.u32.u64 %0, t; }" : "=r"(a) : "l"(p));
    return a;
}
__device__ __forceinline__ void mma_bf16(float* d, const uint32_t* a, const uint32_t* b) {
    asm volatile(
        "mma.sync.aligned.m16n8k16.row.col.f32.bf16.bf16.f32 "
        "{%0,%1,%2,%3}, {%4,%5,%6,%7}, {%8,%9}, {%0,%1,%2,%3};"
        : "+f"(d[0]), "+f"(d[1]), "+f"(d[2]), "+f"(d[3])
        : "r"(a[0]), "r"(a[1]), "r"(a[2]), "r"(a[3]), "r"(b[0]), "r"(b[1]));
}
__device__ __forceinline__ void ldm4(uint32_t* r, uint32_t addr) {
    asm volatile("ldmatrix.sync.aligned.m8n8.x4.shared.b16 {%0,%1,%2,%3}, [%4];"
                 : "=r"(r[0]), "=r"(r[1]), "=r"(r[2]), "=r"(r[3]) : "r"(addr));
}
__device__ __forceinline__ void ldm4t(uint32_t* r, uint32_t addr) {
    asm volatile("ldmatrix.sync.aligned.m8n8.x4.trans.shared.b16 {%0,%1,%2,%3}, [%4];"
                 : "=r"(r[0]), "=r"(r[1]), "=r"(r[2]), "=r"(r[3]) : "r"(addr));
}
__device__ __forceinline__ void cp16(uint32_t dst, const void* src) {
    uint64_t gp;
    asm("cvta.to.global.u64 %0, %1;" : "=l"(gp) : "l"(src));
    asm volatile("cp.async.cg.shared.global [%0], [%1], 16;" :: "r"(dst), "l"(gp));
}
#define SWZ(o) ((o) ^ (((o) >> 3) & 0x70))

// smem layout per stage (bf16, 128B swizzled rows)
#define SM_AH 0u          // 128 x 64 bf16 = 16384 B
#define SM_AL 16384u
#define SM_BH 32768u      // 64 x 64 bf16 = 8192 B
#define SM_BL 40960u
#define STAGE 49152u
#define SMEM_GEMM 98304   // 2 stages

// ============================================================ weight split (once)
__global__ void split_w_kernel(const float* __restrict__ Wq, const float* __restrict__ Wkv,
                               const float* __restrict__ Wo) {
    int idx = blockIdx.x * 256 + threadIdx.x;
    float v;
    if (idx < WKV_BASE)       v = Wq[idx];
    else if (idx < WO_BASE)   v = Wkv[idx - WKV_BASE];
    else                      v = Wo[idx - WO_BASE];
    uint16_t h, l;
    split1(v, h, l);
    g_wh[idx] = __ushort_as_bfloat16(h);
    g_wl[idx] = __ushort_as_bfloat16(l);
}

// ============================================================ encoder
__global__ void encode_kernel(const float* __restrict__ x, const float* __restrict__ noise,
                              const float* __restrict__ rnd, const float* __restrict__ Wenc,
                              const float* __restrict__ pos) {
    int t = blockIdx.x, c = threadIdx.x;
    float a = x[t] + SIGMA * noise[t];
    float r = rnd[t];
    float v = tanhf(a * Wenc[c] + r * Wenc[C + c]) + pos[(t % 160) * C + c];
    uint16_t h, l;
    split1(v, h, l);
    g_hh[t * C + c] = __ushort_as_bfloat16(h);
    g_hl[t * C + c] = __ushort_as_bfloat16(l);
}

// ============================================================ warp-MMA GEMM (ldmatrix + cp.async)
// D[128 x 64chunk] = A[128 x 256] @ W[256 x 64chunk], 3-term bf16 hi/lo split.
// MODE 0: A=g_hh/g_hl, dst=g_qkv ; MODE 1: A=g_oh/g_ol, g_acc=D+b ;
// MODE 2: g_acc+=D+b ; MODE 3: g_h=leaky(g_acc+D+b) and split into g_hh/g_hl
template <int MODE>
__global__ __launch_bounds__(256, 2) void gemm3(
    int b0_off, int ldb0, int nsplit, int b1_off, int ldb1,
    const float* __restrict__ bias) {
    extern __shared__ char sm[];
    uint32_t smb = s2u(sm);
    int tid = threadIdx.x, wid = tid >> 5, lane = tid & 31;
    int g = lane >> 2, t4 = lane & 3;
    int wm = (wid >> 1) * 32, wn = (wid & 1) * 32;
    int nc = blockIdx.x, m0 = blockIdx.y * 128;
    const __nv_bfloat16* Agh = (MODE == 0) ? g_hh : g_oh;
    const __nv_bfloat16* Agl = (MODE == 0) ? g_hl : g_ol;
    int boff, ldb;
    if (nc < nsplit) { boff = b0_off + nc * 64; ldb = ldb0; }
    else             { boff = b1_off + (nc - nsplit) * 64; ldb = ldb1; }

    auto issue = [&](int kc, int s) {
        uint32_t base = smb + s * STAGE;
        int k0 = kc * 64;
        #pragma unroll
        for (int i = 0; i < 8; i++) {               // A hi+lo: 2048 x 16B segs
            int seg = tid + i * 256;
            int half = seg >> 10;
            int r = (seg & 1023) >> 3;
            int c8 = seg & 7;
            uint32_t off = (uint32_t)(r * 128 + c8 * 16);
            uint32_t dst = base + (half ? SM_AL : SM_AH) + SWZ(off);
            cp16(dst, (half ? Agl : Agh) + (m0 + r) * 256 + k0 + c8 * 8);
        }
        #pragma unroll
        for (int i = 0; i < 4; i++) {               // B hi+lo: 1024 x 16B segs
            int seg = tid + i * 256;
            int half = seg >> 9;
            int r = (seg & 511) >> 3;
            int c8 = seg & 7;
            uint32_t off = (uint32_t)(r * 128 + c8 * 16);
            uint32_t dst = base + (half ? SM_BL : SM_BH) + SWZ(off);
            cp16(dst, (half ? g_wl : g_wh) + boff + (k0 + r) * ldb + c8 * 8);
        }
        asm volatile("cp.async.commit_group;");
    };

    float d[2][4][4];
    #pragma unroll
    for (int mi = 0; mi < 2; mi++)
        #pragma unroll
        for (int ni = 0; ni < 4; ni++)
            #pragma unroll
            for (int r = 0; r < 4; r++) d[mi][ni][r] = 0.f;

    // per-lane ldmatrix address components
    int lr = lane & 7, tsel = lane >> 3;
    int a_row = wm + (tsel & 1) * 8 + lr;            // + mi*16
    int a_cb = (tsel >> 1) * 16;                     // + ks*32 (bytes)
    int b_row = (tsel & 1) * 8 + lr;                 // + ks*16
    int b_cb0 = (wn + (tsel >> 1) * 8) * 2;          // + p*32 (bytes)

    issue(0, 0);
    #pragma unroll
    for (int kc = 0; kc < 4; kc++) {
        asm volatile("cp.async.wait_group 0;" ::: "memory");
        __syncthreads();
        if (kc < 3) issue(kc + 1, (kc + 1) & 1);
        uint32_t base = smb + (kc & 1) * STAGE;

        #pragma unroll
        for (int ks = 0; ks < 4; ks++) {
            uint32_t ah[2][4], al[2][4], bh[2][4], bl[2][4];
            #pragma unroll
            for (int mi = 0; mi < 2; mi++) {
                uint32_t off = (uint32_t)((a_row + mi * 16) * 128 + ks * 32 + a_cb);
                ldm4(ah[mi], base + SM_AH + SWZ(off));
                ldm4(al[mi], base + SM_AL + SWZ(off));
            }
            #pragma unroll
            for (int p = 0; p < 2; p++) {
                uint32_t off = (uint32_t)((ks * 16 + b_row) * 128 + b_cb0 + p * 32);
                ldm4t(bh[p], base + SM_BH + SWZ(off));
                ldm4t(bl[p], base + SM_BL + SWZ(off));
            }
            #pragma unroll
            for (int mi = 0; mi < 2; mi++)
                #pragma unroll
                for (int ni = 0; ni < 4; ni++) {
                    const uint32_t* bhf = &bh[ni >> 1][(ni & 1) * 2];
                    const uint32_t* blf = &bl[ni >> 1][(ni & 1) * 2];
                    mma_bf16(d[mi][ni], ah[mi], bhf);
                    mma_bf16(d[mi][ni], al[mi], bhf);
                    mma_bf16(d[mi][ni], ah[mi], blf);
                }
        }
        __syncthreads();
    }

    // ---- epilogue ----
    #pragma unroll
    for (int mi = 0; mi < 2; mi++) {
        #pragma unroll
        for (int ni = 0; ni < 4; ni++) {
            #pragma unroll
            for (int half = 0; half < 2; half++) {
                int row = m0 + wm + mi * 16 + g + half * 8;
                int col = wn + ni * 8 + 2 * t4;
                float v0 = d[mi][ni][half * 2];
                float v1 = d[mi][ni][half * 2 + 1];
                if (MODE == 0) {
                    *(float2*)(g_qkv + row * 768 + nc * 64 + col) = make_float2(v0, v1);
                } else {
                    int n0 = nc * 64 + col;
                    v0 += __ldg(bias + n0);
                    v1 += __ldg(bias + n0 + 1);
                    float* ap = g_acc + row * 256 + n0;
                    if (MODE == 1) {
                        *(float2*)ap = make_float2(v0, v1);
                    } else if (MODE == 2) {
                        float2 a = *(const float2*)ap;
                        *(float2*)ap = make_float2(a.x + v0, a.y + v1);
                    } else {
                        float2 a = *(const float2*)ap;
                        float s0 = a.x + v0, s1 = a.y + v1;
                        float o0 = s0 >= 0.f ? s0 : LEAK * s0;
                        float o1 = s1 >= 0.f ? s1 : LEAK * s1;
                        *(float2*)(g_h + row * 256 + n0) = make_float2(o0, o1);
                        uint16_t h0, l0, h1, l1;
                        split1(o0, h0, l0);
                        split1(o1, h1, l1);
                        *(uint32_t*)(g_hh + row * 256 + n0) = (uint32_t)h0 | ((uint32_t)h1 << 16);
                        *(uint32_t*)(g_hl + row * 256 + n0) = (uint32_t)l0 | ((uint32_t)l1 << 16);
                    }
                }
            }
        }
    }
}

// ============================================================ attention (fp32 in, split bf16 out)
template <int T, int G, int AXIS>
__global__ __launch_bounds__(256, 2) void attn_kernel() {
    constexpr int TT = T * G;
    extern __shared__ char smem_raw[];
    float* qs = (float*)smem_raw;       // [TT][256]
    float* ks = qs + TT * C;
    float* vs = ks + TT * C;
    float* probs = vs + TT * C;         // [G][16][T][T]
    int* s_tok = (int*)(probs + G * 16 * T * T);

    int tid = threadIdx.x;

    if (tid < TT) {
        int gi = tid / T, t = tid % T;
        int g = blockIdx.x * G + gi;
        int base, stride;
        if (AXIS == 1)      { base = (g / 20) * 160 + (g % 20); stride = 20; }
        else if (AXIS == 2) { int b = g / 40, r = g % 40;
                              base = b * 160 + (r / 5) * 20 + (r % 5); stride = 5; }
        else                { base = (g / 32) * 160 + (g % 32) * 5; stride = 1; }
        s_tok[tid] = base + t * stride;
    }
    __syncthreads();

    #pragma unroll
    for (int r = 0; r < TT; r++) {
        int base = s_tok[r] * 768;
        qs[r * C + tid] = g_qkv[base + tid];
        ks[r * C + tid] = g_qkv[base + 256 + tid];
        vs[r * C + tid] = g_qkv[base + 512 + tid];
    }
    __syncthreads();

    for (int i = tid; i < G * 16 * T * T; i += 256) {
        int gi = i / (16 * T * T);
        int r = i % (16 * T * T);
        int head = r / (T * T);
        int rr = r % (T * T);
        int tq = rr / T, ts = rr % T;
        const float* qrow = qs + (gi * T + tq) * C + head * 16;
        const float* krow = ks + (gi * T + ts) * C + head * 16;
        float s = 0.f;
        #pragma unroll
        for (int d = 0; d < 16; d++) s += qrow[d] * krow[d];
        probs[i] = 0.25f * s;
    }
    __syncthreads();

    for (int i = tid; i < G * 16 * T; i += 256) {
        float* row = probs + i * T;
        float m = row[0];
        #pragma unroll
        for (int s = 1; s < T; s++) m = fmaxf(m, row[s]);
        float e[T];
        float sum = 0.f;
        #pragma unroll
        for (int s = 0; s < T; s++) { e[s] = expf(row[s] - m); sum += e[s]; }
        float inv = 1.f / sum;
        #pragma unroll
        for (int s = 0; s < T; s++) row[s] = e[s] * inv;
    }
    __syncthreads();

    int head = tid >> 4;
    #pragma unroll
    for (int tt = 0; tt < TT; tt++) {
        int gi = tt / T, t = tt % T;
        const float* pr = probs + ((gi * 16 + head) * T + t) * T;
        float o = 0.f;
        #pragma unroll
        for (int s = 0; s < T; s++) o += pr[s] * vs[(gi * T + s) * C + tid];
        uint16_t h, l;
        split1(o, h, l);
        g_oh[s_tok[tt] * C + tid] = __ushort_as_bfloat16(h);
        g_ol[s_tok[tt] * C + tid] = __ushort_as_bfloat16(l);
    }
}

// ============================================================ decoder
__global__ void decode_kernel(const float* __restrict__ Wd, const float* __restrict__ bd,
                              float* __restrict__ out) {
    int t = blockIdx.x * 8 + (threadIdx.x >> 5);
    int lane = threadIdx.x & 31;
    const float* hr = g_h + t * C;
    float s = 0.f;
    #pragma unroll
    for (int c = lane; c < C; c += 32) s += hr[c] * Wd[c];
    #pragma unroll
    for (int o = 16; o > 0; o >>= 1) s += __shfl_xor_sync(0xffffffffu, s, o);
    if (lane == 0) out[t] = 1.f / (1.f + expf(-(s + bd[0])));
}

// ============================================================ launch
static constexpr int attn_smem(int T, int G) {
    int TT = T * G;
    return TT * C * 3 * 4 + G * 16 * T * T * 4 + TT * 4;
}

extern "C" void kernel_launch(void* const* d_in, const int* in_sizes, int n_in,
                              void* d_out, int out_size) {
    const float* x     = (const float*)d_in[0];
    const float* noise = (const float*)d_in[1];
    const float* rnd   = (const float*)d_in[2];
    const float* Wenc  = (const float*)d_in[3];
    const float* pos   = (const float*)d_in[4];
    const float* Wq    = (const float*)d_in[5];
    const float* Wkv   = (const float*)d_in[6];
    const float* Wo    = (const float*)d_in[7];
    const float* bo    = (const float*)d_in[8];
    const float* Wd    = (const float*)d_in[9];
    const float* bd    = (const float*)d_in[10];
    float* out = (float*)d_out;

    constexpr int SA1 = attn_smem(8, 2);
    constexpr int SA2 = attn_smem(4, 4);
    constexpr int SA3 = attn_smem(5, 4);

    cudaFuncSetAttribute(gemm3<0>, cudaFuncAttributeMaxDynamicSharedMemorySize, SMEM_GEMM);
    cudaFuncSetAttribute(gemm3<1>, cudaFuncAttributeMaxDynamicSharedMemorySize, SMEM_GEMM);
    cudaFuncSetAttribute(gemm3<2>, cudaFuncAttributeMaxDynamicSharedMemorySize, SMEM_GEMM);
    cudaFuncSetAttribute(gemm3<3>, cudaFuncAttributeMaxDynamicSharedMemorySize, SMEM_GEMM);
    cudaFuncSetAttribute(attn_kernel<8, 2, 1>, cudaFuncAttributeMaxDynamicSharedMemorySize, SA1);
    cudaFuncSetAttribute(attn_kernel<4, 4, 2>, cudaFuncAttributeMaxDynamicSharedMemorySize, SA2);
    cudaFuncSetAttribute(attn_kernel<5, 4, 3>, cudaFuncAttributeMaxDynamicSharedMemorySize, SA3);

    split_w_kernel<<<W_TOTAL / 256, 256>>>(Wq, Wkv, Wo);
    encode_kernel<<<N_TOK, 256>>>(x, noise, rnd, Wenc, pos);

    for (int l = 0; l < 2; l++) {
        for (int a = 0; a < 3; a++) {
            int w = l * 3 + a;
            const float* bb = bo + w * C;

            // qkv = h @ [Wq | Wkv]  (12 n-chunks of 64)
            gemm3<0><<<dim3(12, 640), 256, SMEM_GEMM>>>(
                w * 65536, 256, 4, WKV_BASE + w * 131072, 512, nullptr);

            if (a == 0)      attn_kernel<8, 2, 1><<<5120, 256, SA1>>>();
            else if (a == 1) attn_kernel<4, 4, 2><<<5120, 256, SA2>>>();
            else             attn_kernel<5, 4, 3><<<4096, 256, SA3>>>();

            // contrib = o @ Wo + bo, fused with accumulate / leaky (+h split)
            int wo_off = WO_BASE + w * 65536;
            if (a == 0)      gemm3<1><<<dim3(4, 640), 256, SMEM_GEMM>>>(wo_off, 256, 4, 0, 0, bb);
            else if (a == 1) gemm3<2><<<dim3(4, 640), 256, SMEM_GEMM>>>(wo_off, 256, 4, 0, 0, bb);
            else             gemm3<3><<<dim3(4, 640), 256, SMEM_GEMM>>>(wo_off, 256, 4, 0, 0, bb);
        }
    }

    decode_kernel<<<10240, 256>>>(Wd, bd, out);
}

// round 9
// speedup vs baseline: 2.5322x; 1.1585x over previous
#include <cuda_runtime.h>
#include <cuda_bf16.h>
#include <cstdint>

#define N_TOK 81920
#define C 256
#define SIGMA 0.0001f
#define LEAK 0.2f

// ---- scratch (device globals: no allocs allowed) ----
__device__ float g_h[N_TOK * C];          // final hidden (for decode)
__device__ float g_acc[N_TOK * C];        // axial-sum accumulator
__device__ float g_qkv[N_TOK * 768];      // q|k|v scratch (fp32)
__device__ __nv_bfloat16 g_hh[N_TOK * C]; // hidden state hi/lo split (bf16)
__device__ __nv_bfloat16 g_hl[N_TOK * C];
__device__ __nv_bfloat16 g_oh[N_TOK * C]; // attn output hi/lo split (bf16)
__device__ __nv_bfloat16 g_ol[N_TOK * C];
#define W_TOTAL 1572864                   // Wq(393216) | Wkv(786432) | Wo(393216)
#define WKV_BASE 393216
#define WO_BASE 1179648
__device__ __nv_bfloat16 g_wh[W_TOTAL];
__device__ __nv_bfloat16 g_wl[W_TOTAL];

// ============================================================ helpers
__device__ __forceinline__ void split1(float a, uint16_t& h, uint16_t& l) {
    __nv_bfloat16 ha = __float2bfloat16(a);
    float ra = a - __bfloat162float(ha);
    __nv_bfloat16 la = __float2bfloat16(ra);
    h = __bfloat16_as_ushort(ha);
    l = __bfloat16_as_ushort(la);
}
__device__ __forceinline__ uint32_t s2u(const void* p) {
    uint32_t a;
    asm("{ .reg .u64 t; cvta.to.shared.u64 t, %1; cvt.u32.u64 %0, t; }" : "=r"(a) : "l"(p));
    return a;
}
__device__ __forceinline__ void mma_bf16(float* d, const uint32_t* a, const uint32_t* b) {
    asm volatile(
        "mma.sync.aligned.m16n8k16.row.col.f32.bf16.bf16.f32 "
        "{%0,%1,%2,%3}, {%4,%5,%6,%7}, {%8,%9}, {%0,%1,%2,%3};"
        : "+f"(d[0]), "+f"(d[1]), "+f"(d[2]), "+f"(d[3])
        : "r"(a[0]), "r"(a[1]), "r"(a[2]), "r"(a[3]), "r"(b[0]), "r"(b[1]));
}
__device__ __forceinline__ void ldm4(uint32_t* r, uint32_t addr) {
    asm volatile("ldmatrix.sync.aligned.m8n8.x4.shared.b16 {%0,%1,%2,%3}, [%4];"
                 : "=r"(r[0]), "=r"(r[1]), "=r"(r[2]), "=r"(r[3]) : "r"(addr));
}
__device__ __forceinline__ void ldm4t(uint32_t* r, uint32_t addr) {
    asm volatile("ldmatrix.sync.aligned.m8n8.x4.trans.shared.b16 {%0,%1,%2,%3}, [%4];"
                 : "=r"(r[0]), "=r"(r[1]), "=r"(r[2]), "=r"(r[3]) : "r"(addr));
}
__device__ __forceinline__ void cp16(uint32_t dst, const void* src) {
    uint64_t gp;
    asm("cvta.to.global.u64 %0, %1;" : "=l"(gp) : "l"(src));
    asm volatile("cp.async.cg.shared.global [%0], [%1], 16;" :: "r"(dst), "l"(gp));
}
#define SWZ(o) ((o) ^ (((o) >> 3) & 0x70))

// smem layout per stage (bf16, 128B swizzled rows)
#define SM_AH 0u          // 128 x 64 bf16 = 16384 B
#define SM_AL 16384u
#define SM_BH 32768u      // 64 x 64 bf16 = 8192 B
#define SM_BL 40960u
#define STAGE 49152u
#define SMEM_GEMM 98304   // 2 stages

// ============================================================ weight split (once)
__global__ void split_w_kernel(const float* __restrict__ Wq, const float* __restrict__ Wkv,
                               const float* __restrict__ Wo) {
    int idx = blockIdx.x * 256 + threadIdx.x;
    float v;
    if (idx < WKV_BASE)       v = Wq[idx];
    else if (idx < WO_BASE)   v = Wkv[idx - WKV_BASE];
    else                      v = Wo[idx - WO_BASE];
    uint16_t h, l;
    split1(v, h, l);
    g_wh[idx] = __ushort_as_bfloat16(h);
    g_wl[idx] = __ushort_as_bfloat16(l);
}

// ============================================================ encoder
__global__ void encode_kernel(const float* __restrict__ x, const float* __restrict__ noise,
                              const float* __restrict__ rnd, const float* __restrict__ Wenc,
                              const float* __restrict__ pos) {
    int t = blockIdx.x, c = threadIdx.x;
    float a = x[t] + SIGMA * noise[t];
    float r = rnd[t];
    float v = tanhf(a * Wenc[c] + r * Wenc[C + c]) + pos[(t % 160) * C + c];
    uint16_t h, l;
    split1(v, h, l);
    g_hh[t * C + c] = __ushort_as_bfloat16(h);
    g_hl[t * C + c] = __ushort_as_bfloat16(l);
}

// ============================================================ warp-MMA GEMM (ldmatrix + cp.async)
// D[128 x 64chunk] = A[128 x 256] @ W[256 x 64chunk], 3-term bf16 hi/lo split.
// MODE 0: A=g_hh/g_hl, dst=g_qkv ; MODE 1: A=g_oh/g_ol, g_acc=D+b ;
// MODE 2: g_acc+=D+b ; MODE 3: g_h=leaky(g_acc+D+b) and split into g_hh/g_hl
template <int MODE>
__global__ __launch_bounds__(256, 2) void gemm3(
    int b0_off, int ldb0, int nsplit, int b1_off, int ldb1,
    const float* __restrict__ bias) {
    extern __shared__ char sm[];
    uint32_t smb = s2u(sm);
    int tid = threadIdx.x, wid = tid >> 5, lane = tid & 31;
    int g = lane >> 2, t4 = lane & 3;
    int wm = (wid >> 1) * 32, wn = (wid & 1) * 32;
    int nc = blockIdx.x, m0 = blockIdx.y * 128;
    const __nv_bfloat16* Agh = (MODE == 0) ? g_hh : g_oh;
    const __nv_bfloat16* Agl = (MODE == 0) ? g_hl : g_ol;
    int boff, ldb;
    if (nc < nsplit) { boff = b0_off + nc * 64; ldb = ldb0; }
    else             { boff = b1_off + (nc - nsplit) * 64; ldb = ldb1; }

    auto issue = [&](int kc, int s) {
        uint32_t base = smb + s * STAGE;
        int k0 = kc * 64;
        #pragma unroll
        for (int i = 0; i < 8; i++) {               // A hi+lo: 2048 x 16B segs
            int seg = tid + i * 256;
            int half = seg >> 10;
            int r = (seg & 1023) >> 3;
            int c8 = seg & 7;
            uint32_t off = (uint32_t)(r * 128 + c8 * 16);
            uint32_t dst = base + (half ? SM_AL : SM_AH) + SWZ(off);
            cp16(dst, (half ? Agl : Agh) + (m0 + r) * 256 + k0 + c8 * 8);
        }
        #pragma unroll
        for (int i = 0; i < 4; i++) {               // B hi+lo: 1024 x 16B segs
            int seg = tid + i * 256;
            int half = seg >> 9;
            int r = (seg & 511) >> 3;
            int c8 = seg & 7;
            uint32_t off = (uint32_t)(r * 128 + c8 * 16);
            uint32_t dst = base + (half ? SM_BL : SM_BH) + SWZ(off);
            cp16(dst, (half ? g_wl : g_wh) + boff + (k0 + r) * ldb + c8 * 8);
        }
        asm volatile("cp.async.commit_group;");
    };

    float d[2][4][4];
    #pragma unroll
    for (int mi = 0; mi < 2; mi++)
        #pragma unroll
        for (int ni = 0; ni < 4; ni++)
            #pragma unroll
            for (int r = 0; r < 4; r++) d[mi][ni][r] = 0.f;

    // per-lane ldmatrix address components
    int lr = lane & 7, tsel = lane >> 3;
    int a_row = wm + (tsel & 1) * 8 + lr;            // + mi*16
    int a_cb = (tsel >> 1) * 16;                     // + ks*32 (bytes)
    int b_row = (tsel & 1) * 8 + lr;                 // + ks*16
    int b_cb0 = (wn + (tsel >> 1) * 8) * 2;          // + p*32 (bytes)

    issue(0, 0);
    #pragma unroll
    for (int kc = 0; kc < 4; kc++) {
        asm volatile("cp.async.wait_group 0;" ::: "memory");
        __syncthreads();
        if (kc < 3) issue(kc + 1, (kc + 1) & 1);
        uint32_t base = smb + (kc & 1) * STAGE;

        #pragma unroll
        for (int ks = 0; ks < 4; ks++) {
            uint32_t ah[2][4], al[2][4], bh[2][4], bl[2][4];
            #pragma unroll
            for (int mi = 0; mi < 2; mi++) {
                uint32_t off = (uint32_t)((a_row + mi * 16) * 128 + ks * 32 + a_cb);
                ldm4(ah[mi], base + SM_AH + SWZ(off));
                ldm4(al[mi], base + SM_AL + SWZ(off));
            }
            #pragma unroll
            for (int p = 0; p < 2; p++) {
                uint32_t off = (uint32_t)((ks * 16 + b_row) * 128 + b_cb0 + p * 32);
                ldm4t(bh[p], base + SM_BH + SWZ(off));
                ldm4t(bl[p], base + SM_BL + SWZ(off));
            }
            #pragma unroll
            for (int mi = 0; mi < 2; mi++)
                #pragma unroll
                for (int ni = 0; ni < 4; ni++) {
                    const uint32_t* bhf = &bh[ni >> 1][(ni & 1) * 2];
                    const uint32_t* blf = &bl[ni >> 1][(ni & 1) * 2];
                    mma_bf16(d[mi][ni], ah[mi], bhf);
                    mma_bf16(d[mi][ni], al[mi], bhf);
                    mma_bf16(d[mi][ni], ah[mi], blf);
                }
        }
        __syncthreads();
    }

    // ---- epilogue ----
    #pragma unroll
    for (int mi = 0; mi < 2; mi++) {
        #pragma unroll
        for (int ni = 0; ni < 4; ni++) {
            #pragma unroll
            for (int half = 0; half < 2; half++) {
                int row = m0 + wm + mi * 16 + g + half * 8;
                int col = wn + ni * 8 + 2 * t4;
                float v0 = d[mi][ni][half * 2];
                float v1 = d[mi][ni][half * 2 + 1];
                if (MODE == 0) {
                    *(float2*)(g_qkv + row * 768 + nc * 64 + col) = make_float2(v0, v1);
                } else {
                    int n0 = nc * 64 + col;
                    v0 += __ldg(bias + n0);
                    v1 += __ldg(bias + n0 + 1);
                    float* ap = g_acc + row * 256 + n0;
                    if (MODE == 1) {
                        *(float2*)ap = make_float2(v0, v1);
                    } else if (MODE == 2) {
                        float2 a = *(const float2*)ap;
                        *(float2*)ap = make_float2(a.x + v0, a.y + v1);
                    } else {
                        float2 a = *(const float2*)ap;
                        float s0 = a.x + v0, s1 = a.y + v1;
                        float o0 = s0 >= 0.f ? s0 : LEAK * s0;
                        float o1 = s1 >= 0.f ? s1 : LEAK * s1;
                        *(float2*)(g_h + row * 256 + n0) = make_float2(o0, o1);
                        uint16_t h0, l0, h1, l1;
                        split1(o0, h0, l0);
                        split1(o1, h1, l1);
                        *(uint32_t*)(g_hh + row * 256 + n0) = (uint32_t)h0 | ((uint32_t)h1 << 16);
                        *(uint32_t*)(g_hl + row * 256 + n0) = (uint32_t)l0 | ((uint32_t)l1 << 16);
                    }
                }
            }
        }
    }
}

// ============================================================ attention (fp32 in, split bf16 out)
// q/k/v held TRANSPOSED in smem: [c][token], rows padded to TTP (gcd(TTP,32)=1)
// -> conflict-free staging stores, broadcast q / unit-stride k in logits,
//    conflict-free v reads in the AV phase.
template <int T, int G, int AXIS>
__global__ __launch_bounds__(256, 2) void attn_kernel() {
    constexpr int TT = T * G;
    constexpr int TTP = TT + 1;          // 17, 17, 21 -> all coprime with 32
    extern __shared__ char smem_raw[];
    float* qsT = (float*)smem_raw;       // [256][TTP]
    float* ksT = qsT + C * TTP;
    float* vsT = ksT + C * TTP;
    float* probs = vsT + C * TTP;        // [G][16][T][T]
    int* s_tok = (int*)(probs + G * 16 * T * T);

    int tid = threadIdx.x;

    if (tid < TT) {
        int gi = tid / T, t = tid % T;
        int g = blockIdx.x * G + gi;
        int base, stride;
        if (AXIS == 1)      { base = (g / 20) * 160 + (g % 20); stride = 20; }
        else if (AXIS == 2) { int b = g / 40, r = g % 40;
                              base = b * 160 + (r / 5) * 20 + (r % 5); stride = 5; }
        else                { base = (g / 32) * 160 + (g % 32) * 5; stride = 1; }
        s_tok[tid] = base + t * stride;
    }
    __syncthreads();

    // stage transposed: coalesced LDG, stride-TTP STS (conflict-free)
    #pragma unroll
    for (int r = 0; r < TT; r++) {
        int base = s_tok[r] * 768;
        qsT[tid * TTP + r] = g_qkv[base + tid];
        ksT[tid * TTP + r] = g_qkv[base + 256 + tid];
        vsT[tid * TTP + r] = g_qkv[base + 512 + tid];
    }
    __syncthreads();

    // logits: q broadcast across ts, k unit-stride in ts
    for (int i = tid; i < G * 16 * T * T; i += 256) {
        int gi = i / (16 * T * T);
        int r = i % (16 * T * T);
        int head = r / (T * T);
        int rr = r % (T * T);
        int tq = rr / T, ts = rr % T;
        const float* qp = qsT + head * 16 * TTP + gi * T + tq;
        const float* kp = ksT + head * 16 * TTP + gi * T + ts;
        float s = 0.f;
        #pragma unroll
        for (int d = 0; d < 16; d++) s += qp[d * TTP] * kp[d * TTP];
        probs[i] = 0.25f * s;
    }
    __syncthreads();

    for (int i = tid; i < G * 16 * T; i += 256) {
        float* row = probs + i * T;
        float m = row[0];
        #pragma unroll
        for (int s = 1; s < T; s++) m = fmaxf(m, row[s]);
        float e[T];
        float sum = 0.f;
        #pragma unroll
        for (int s = 0; s < T; s++) { e[s] = expf(row[s] - m); sum += e[s]; }
        float inv = 1.f / sum;
        #pragma unroll
        for (int s = 0; s < T; s++) row[s] = e[s] * inv;
    }
    __syncthreads();

    // AV: per-thread channel row of vsT (stride-TTP across threads: conflict-free)
    int head = tid >> 4;
    const float* vrow = vsT + tid * TTP;
    #pragma unroll
    for (int tt = 0; tt < TT; tt++) {
        int gi = tt / T, t = tt % T;
        const float* pr = probs + ((gi * 16 + head) * T + t) * T;
        float o = 0.f;
        #pragma unroll
        for (int s = 0; s < T; s++) o += pr[s] * vrow[gi * T + s];
        uint16_t h, l;
        split1(o, h, l);
        g_oh[s_tok[tt] * C + tid] = __ushort_as_bfloat16(h);
        g_ol[s_tok[tt] * C + tid] = __ushort_as_bfloat16(l);
    }
}

// ============================================================ decoder
__global__ void decode_kernel(const float* __restrict__ Wd, const float* __restrict__ bd,
                              float* __restrict__ out) {
    int t = blockIdx.x * 8 + (threadIdx.x >> 5);
    int lane = threadIdx.x & 31;
    const float* hr = g_h + t * C;
    float s = 0.f;
    #pragma unroll
    for (int c = lane; c < C; c += 32) s += hr[c] * Wd[c];
    #pragma unroll
    for (int o = 16; o > 0; o >>= 1) s += __shfl_xor_sync(0xffffffffu, s, o);
    if (lane == 0) out[t] = 1.f / (1.f + expf(-(s + bd[0])));
}

// ============================================================ launch
static constexpr int attn_smem(int T, int G) {
    int TTP = T * G + 1;
    return 3 * C * TTP * 4 + G * 16 * T * T * 4 + T * G * 4;
}

extern "C" void kernel_launch(void* const* d_in, const int* in_sizes, int n_in,
                              void* d_out, int out_size) {
    const float* x     = (const float*)d_in[0];
    const float* noise = (const float*)d_in[1];
    const float* rnd   = (const float*)d_in[2];
    const float* Wenc  = (const float*)d_in[3];
    const float* pos   = (const float*)d_in[4];
    const float* Wq    = (const float*)d_in[5];
    const float* Wkv   = (const float*)d_in[6];
    const float* Wo    = (const float*)d_in[7];
    const float* bo    = (const float*)d_in[8];
    const float* Wd    = (const float*)d_in[9];
    const float* bd    = (const float*)d_in[10];
    float* out = (float*)d_out;

    constexpr int SA1 = attn_smem(8, 2);
    constexpr int SA2 = attn_smem(4, 4);
    constexpr int SA3 = attn_smem(5, 4);

    cudaFuncSetAttribute(gemm3<0>, cudaFuncAttributeMaxDynamicSharedMemorySize, SMEM_GEMM);
    cudaFuncSetAttribute(gemm3<1>, cudaFuncAttributeMaxDynamicSharedMemorySize, SMEM_GEMM);
    cudaFuncSetAttribute(gemm3<2>, cudaFuncAttributeMaxDynamicSharedMemorySize, SMEM_GEMM);
    cudaFuncSetAttribute(gemm3<3>, cudaFuncAttributeMaxDynamicSharedMemorySize, SMEM_GEMM);
    cudaFuncSetAttribute(attn_kernel<8, 2, 1>, cudaFuncAttributeMaxDynamicSharedMemorySize, SA1);
    cudaFuncSetAttribute(attn_kernel<4, 4, 2>, cudaFuncAttributeMaxDynamicSharedMemorySize, SA2);
    cudaFuncSetAttribute(attn_kernel<5, 4, 3>, cudaFuncAttributeMaxDynamicSharedMemorySize, SA3);

    split_w_kernel<<<W_TOTAL / 256, 256>>>(Wq, Wkv, Wo);
    encode_kernel<<<N_TOK, 256>>>(x, noise, rnd, Wenc, pos);

    for (int l = 0; l < 2; l++) {
        for (int a = 0; a < 3; a++) {
            int w = l * 3 + a;
            const float* bb = bo + w * C;

            // qkv = h @ [Wq | Wkv]  (12 n-chunks of 64)
            gemm3<0><<<dim3(12, 640), 256, SMEM_GEMM>>>(
                w * 65536, 256, 4, WKV_BASE + w * 131072, 512, nullptr);

            if (a == 0)      attn_kernel<8, 2, 1><<<5120, 256, SA1>>>();
            else if (a == 1) attn_kernel<4, 4, 2><<<5120, 256, SA2>>>();
            else             attn_kernel<5, 4, 3><<<4096, 256, SA3>>>();

            // contrib = o @ Wo + bo, fused with accumulate / leaky (+h split)
            int wo_off = WO_BASE + w * 65536;
            if (a == 0)      gemm3<1><<<dim3(4, 640), 256, SMEM_GEMM>>>(wo_off, 256, 4, 0, 0, bb);
            else if (a == 1) gemm3<2><<<dim3(4, 640), 256, SMEM_GEMM>>>(wo_off, 256, 4, 0, 0, bb);
            else             gemm3<3><<<dim3(4, 640), 256, SMEM_GEMM>>>(wo_off, 256, 4, 0, 0, bb);
        }
    }

    decode_kernel<<<10240, 256>>>(Wd, bd, out);
}